// round 7
// baseline (speedup 1.0000x reference)
#include <cuda_runtime.h>
#include <cuda_bf16.h>
#include <cstdint>

#define D_MODEL 768
#define KP_MODEL 384            // D/2 (u32 pairs)
#define N_HEADS 12
#define HD      64
#define B_SZ    4
#define T_SEQ   2048
#define M_TOK   (B_SZ * T_SEQ)  // 8192
#define N_QKV   (3 * D_MODEL)   // 2304

// ---------------- static device scratch (hi/lo bf16-pair planes, u32) -------
__device__ unsigned g_xh[(size_t)M_TOK * KP_MODEL],  g_xl[(size_t)M_TOK * KP_MODEL];
__device__ unsigned g_wqh[(size_t)KP_MODEL * N_QKV], g_wql[(size_t)KP_MODEL * N_QKV];
__device__ unsigned g_woh[(size_t)KP_MODEL * D_MODEL], g_wol[(size_t)KP_MODEL * D_MODEL];
// head-major [B][H][T][32] pair planes
#define HM_SZ ((size_t)B_SZ * N_HEADS * T_SEQ * 32)
__device__ unsigned g_qh[HM_SZ], g_ql[HM_SZ];
__device__ unsigned g_kh[HM_SZ], g_kl[HM_SZ];
__device__ unsigned g_vh[HM_SZ], g_vl[HM_SZ];
// V transposed planes: [B][H][T/2 keypairs][64 d] u32
__device__ unsigned g_vth[HM_SZ], g_vtl[HM_SZ];
// attention output planes (A-operand layout for out-proj)
__device__ unsigned g_ah[(size_t)M_TOK * KP_MODEL], g_al[(size_t)M_TOK * KP_MODEL];

// ---------------------------------------------------------------------------
__device__ __forceinline__ void mma_bf16(float c[4], const unsigned a[4],
                                         unsigned b0, unsigned b1)
{
    asm volatile(
        "mma.sync.aligned.m16n8k16.row.col.f32.bf16.bf16.f32 "
        "{%0,%1,%2,%3}, {%4,%5,%6,%7}, {%8,%9}, {%0,%1,%2,%3};\n"
        : "+f"(c[0]), "+f"(c[1]), "+f"(c[2]), "+f"(c[3])
        : "r"(a[0]), "r"(a[1]), "r"(a[2]), "r"(a[3]), "r"(b0), "r"(b1));
}

__device__ __forceinline__ unsigned pack_bf2(float e_lo, float e_hi)
{
    __nv_bfloat162 t = __floats2bfloat162_rn(e_lo, e_hi); // .x -> low half
    return *reinterpret_cast<unsigned*>(&t);
}

__device__ __forceinline__ void split2(float x0, float x1, unsigned& hi, unsigned& lo)
{
    float h0 = __bfloat162float(__float2bfloat16(x0));
    float h1 = __bfloat162float(__float2bfloat16(x1));
    hi = pack_bf2(h0, h1);
    lo = pack_bf2(x0 - h0, x1 - h1);
}

__device__ __forceinline__ void cp16(void* dst_smem, const void* src)
{
    unsigned saddr = (unsigned)__cvta_generic_to_shared(dst_smem);
    asm volatile("cp.async.cg.shared.global [%0], [%1], 16;\n" :: "r"(saddr), "l"(src));
}
__device__ __forceinline__ void cp_commit() { asm volatile("cp.async.commit_group;\n"); }
template <int N>
__device__ __forceinline__ void cp_wait() { asm volatile("cp.async.wait_group %0;\n" :: "n"(N)); }

// ---------------------------------------------------------------------------
// Split kernels (run once per launch; memory-bound, tiny)
// ---------------------------------------------------------------------------
__global__ void split_rowpairs(const float* __restrict__ src,
                               unsigned* __restrict__ H, unsigned* __restrict__ L,
                               int total)
{
    int i = blockIdx.x * blockDim.x + threadIdx.x;
    if (i < total) {
        float2 v = ((const float2*)src)[i];
        unsigned h, l;
        split2(v.x, v.y, h, l);
        H[i] = h; L[i] = l;
    }
}

// Pack pairs along K across two rows of W[K][N] -> planes [K/2][N]
__global__ void split_colpairs(const float* __restrict__ src,
                               unsigned* __restrict__ H, unsigned* __restrict__ L,
                               int N, int total)
{
    int i = blockIdx.x * blockDim.x + threadIdx.x;
    if (i < total) {
        int kp = i / N, n = i - kp * N;
        float a = src[(size_t)(2 * kp) * N + n];
        float b = src[(size_t)(2 * kp + 1) * N + n];
        unsigned h, l;
        split2(a, b, h, l);
        H[i] = h; L[i] = l;
    }
}

// ---------------------------------------------------------------------------
// V transpose: head-major [t][dp] planes -> key-pair-major [kp][d] planes.
// out[kp][d] = bf16x2( V[2kp][d], V[2kp+1][d] ).
// grid (32 ktiles, H, B), 256 thr; tile = 64 keys x 64 dims.
// ---------------------------------------------------------------------------
__global__ __launch_bounds__(256) void vtrans()
{
    __shared__ unsigned sH[64 * 33], sL[64 * 33];
    const int ktile = blockIdx.x, h = blockIdx.y, b = blockIdx.z;
    const int tid = threadIdx.x;
    const size_t in_base  = ((size_t)(b * N_HEADS + h) * T_SEQ + ktile * 64) * 32;
    const size_t out_base = ((size_t)(b * N_HEADS + h) * (T_SEQ / 2) + ktile * 32) * 64;

#pragma unroll
    for (int i = 0; i < 8; i++) {
        int idx = tid + i * 256;        // 2048: t(0..63) x dp(0..31)
        int t = idx >> 5, dp = idx & 31;
        sH[t * 33 + dp] = g_vh[in_base + t * 32 + dp];
        sL[t * 33 + dp] = g_vl[in_base + t * 32 + dp];
    }
    __syncthreads();
#pragma unroll
    for (int i = 0; i < 8; i++) {
        int o = tid + i * 256;          // 2048: kp(0..31) x d(0..63)
        int kp = o >> 6, d = o & 63;
        unsigned sel = (d & 1) ? 0x7632u : 0x5410u;
        unsigned h0 = sH[(2 * kp) * 33 + (d >> 1)];
        unsigned h1 = sH[(2 * kp + 1) * 33 + (d >> 1)];
        g_vth[out_base + o] = __byte_perm(h0, h1, sel);
        unsigned l0 = sL[(2 * kp) * 33 + (d >> 1)];
        unsigned l1 = sL[(2 * kp + 1) * 33 + (d >> 1)];
        g_vtl[out_base + o] = __byte_perm(l0, l1, sel);
    }
}

// ---------------------------------------------------------------------------
// GEMM on pre-split planes. C[M,N] = A @ B (+bias).
// 256 thr = 8 warps (4m x 2n), block tile 256x128, WARP TILE 64x64, BK=32,
// cp.async double-buffered. EPI=0: fp32 out. EPI=1: QKV -> head-major planes.
// ---------------------------------------------------------------------------
#define GA_STR 20
#define GB_STR 136
#define GA_SZ  (256 * GA_STR)           // 5120 u32
#define GB_SZ  (16 * GB_STR)            // 2176 u32
#define GBUF   (2 * GA_SZ + 2 * GB_SZ)  // 14592 u32
#define GEMM_SMEM (2 * GBUF * 4)        // 116736 bytes

template <int EPI>
__global__ __launch_bounds__(256) void gemm_planes(
    const unsigned* __restrict__ Ah, const unsigned* __restrict__ Al,
    const unsigned* __restrict__ Bh, const unsigned* __restrict__ Bl,
    const float* __restrict__ bias, float* __restrict__ Cout,
    int M, int N, int K)
{
    extern __shared__ unsigned sm[];
    const int tid  = threadIdx.x;
    const int lane = tid & 31;
    const int wid  = tid >> 5;
    const int wm   = wid >> 1;      // 0..3 -> 64-row slabs
    const int wn   = wid & 1;       // 0..1 -> 64-col slabs
    const int lq   = lane >> 2;
    const int lr   = lane & 3;
    const int bm = blockIdx.y, bn = blockIdx.x;
    const int KP = K >> 1;

    float acc[4][8][4];
#pragma unroll
    for (int mt = 0; mt < 4; mt++)
#pragma unroll
        for (int n = 0; n < 8; n++)
#pragma unroll
            for (int j = 0; j < 4; j++) acc[mt][n][j] = 0.0f;

    auto load_tile = [&](int kt, int buf) {
        unsigned* AHs = sm + buf * GBUF;
        unsigned* ALs = AHs + GA_SZ;
        unsigned* BHs = ALs + GA_SZ;
        unsigned* BLs = BHs + GB_SZ;
        const int kp0 = kt * 16;
#pragma unroll
        for (int i = 0; i < 4; i++) {
            int idx = tid + i * 256;          // 1024: 256 rows x 4 chunks
            int row = idx >> 2, c4 = (idx & 3) * 4;
            size_t g = (size_t)(bm * 256 + row) * KP + kp0 + c4;
            cp16(&AHs[row * GA_STR + c4], Ah + g);
            cp16(&ALs[row * GA_STR + c4], Al + g);
        }
#pragma unroll
        for (int i = 0; i < 2; i++) {
            int idx = tid + i * 256;          // 512: 16 rows x 32 chunks
            int row = idx >> 5, c4 = (idx & 31) * 4;
            size_t g = (size_t)(kp0 + row) * N + bn * 128 + c4;
            cp16(&BHs[row * GB_STR + c4], Bh + g);
            cp16(&BLs[row * GB_STR + c4], Bl + g);
        }
        cp_commit();
    };

    const int KT = K / 32;
    load_tile(0, 0);

    for (int kt = 0; kt < KT; kt++) {
        int buf = kt & 1;
        if (kt + 1 < KT) {
            load_tile(kt + 1, buf ^ 1);
            cp_wait<1>();
        } else {
            cp_wait<0>();
        }
        __syncthreads();

        unsigned* AHs = sm + buf * GBUF;
        unsigned* ALs = AHs + GA_SZ;
        unsigned* BHs = ALs + GA_SZ;
        unsigned* BLs = BHs + GB_SZ;

#pragma unroll
        for (int kk = 0; kk < 2; kk++) {
            unsigned ah[4][4], al[4][4];
            const int p = kk * 8 + lr;
#pragma unroll
            for (int mt = 0; mt < 4; mt++) {
                int r = wm * 64 + mt * 16 + lq;
                ah[mt][0] = AHs[r * GA_STR + p];
                ah[mt][1] = AHs[(r + 8) * GA_STR + p];
                ah[mt][2] = AHs[r * GA_STR + p + 4];
                ah[mt][3] = AHs[(r + 8) * GA_STR + p + 4];
                al[mt][0] = ALs[r * GA_STR + p];
                al[mt][1] = ALs[(r + 8) * GA_STR + p];
                al[mt][2] = ALs[r * GA_STR + p + 4];
                al[mt][3] = ALs[(r + 8) * GA_STR + p + 4];
            }
#pragma unroll
            for (int n = 0; n < 8; n++) {
                int col = wn * 64 + n * 8 + lq;
                unsigned bh0 = BHs[p * GB_STR + col];
                unsigned bh1 = BHs[(p + 4) * GB_STR + col];
                unsigned bl0 = BLs[p * GB_STR + col];
                unsigned bl1 = BLs[(p + 4) * GB_STR + col];
#pragma unroll
                for (int mt = 0; mt < 4; mt++) {
                    mma_bf16(acc[mt][n], ah[mt], bh0, bh1);
                    mma_bf16(acc[mt][n], ah[mt], bl0, bl1);
                    mma_bf16(acc[mt][n], al[mt], bh0, bh1);
                }
            }
        }
        __syncthreads();
    }

    // ---- epilogue
#pragma unroll
    for (int mt = 0; mt < 4; mt++) {
        int row0 = bm * 256 + wm * 64 + mt * 16 + lq;
#pragma unroll
        for (int n = 0; n < 8; n++) {
            int col = bn * 128 + wn * 64 + n * 8 + 2 * lr;
            float b0 = bias[col], b1 = bias[col + 1];
            float x0 = acc[mt][n][0] + b0, x1 = acc[mt][n][1] + b1;
            float y0 = acc[mt][n][2] + b0, y1 = acc[mt][n][3] + b1;
            if (EPI == 0) {
                *(float2*)&Cout[(size_t)row0 * N + col]       = make_float2(x0, x1);
                *(float2*)&Cout[(size_t)(row0 + 8) * N + col] = make_float2(y0, y1);
            } else {
                int seg = col / D_MODEL;
                int nn  = col - seg * D_MODEL;
                int hh2 = nn >> 6;
                int dp  = (nn & 63) >> 1;
                if (seg == 0) { x0 *= 0.125f; x1 *= 0.125f; y0 *= 0.125f; y1 *= 0.125f; }
                unsigned* H = (seg == 0) ? g_qh : (seg == 1) ? g_kh : g_vh;
                unsigned* L = (seg == 0) ? g_ql : (seg == 1) ? g_kl : g_vl;
                int bb = row0 >> 11, t = row0 & 2047;
                size_t o = ((size_t)(bb * N_HEADS + hh2) * T_SEQ + t) * 32 + dp;
                unsigned hv, lv;
                split2(x0, x1, hv, lv);
                H[o] = hv; L[o] = lv;
                split2(y0, y1, hv, lv);
                H[o + 8 * 32] = hv; L[o + 8 * 32] = lv;
            }
        }
    }
}

// ---------------------------------------------------------------------------
// Flash attention (causal), split-bf16 tensor cores, 128-query tiles.
// 128 thr = 4 warps; warp w owns q rows [w*32, w*32+32).
// Q staged once; K and (pre-transposed) V double-buffered via cp.async.
// Smem (u32): QH/QL[128][36], K bufs 2x{KH/KL[64][36]}, V bufs 2x{VH/VL[32][72]},
//             PH/PL[128][36]   = 36864 u32 = 147456 B
// ---------------------------------------------------------------------------
#define AT_SQ 36
#define AT_SK 36
#define AT_SV 72
#define KBUF_SZ (2 * 64 * AT_SK)    // KH+KL per buffer (4608 u32)
#define VBUF_SZ (2 * 32 * AT_SV)    // VH+VL per buffer (4608 u32)
#define ATTN_SMEM ((2*128*AT_SQ + 2*KBUF_SZ + 2*VBUF_SZ + 2*128*AT_SQ) * 4)

__global__ __launch_bounds__(128) void attn_tc()
{
    extern __shared__ unsigned usm[];
    unsigned* QH = usm;
    unsigned* QL = QH + 128 * AT_SQ;
    unsigned* Kbuf = QL + 128 * AT_SQ;              // 2 x KBUF_SZ
    unsigned* Vbuf = Kbuf + 2 * KBUF_SZ;            // 2 x VBUF_SZ
    unsigned* PH = Vbuf + 2 * VBUF_SZ;
    unsigned* PL = PH + 128 * AT_SQ;

    const int b = blockIdx.z, h = blockIdx.y;
    const int qt = gridDim.x - 1 - blockIdx.x;      // heavy tiles first
    const int tid = threadIdx.x;
    const int w = tid >> 5, lane = tid & 31;
    const int lq = lane >> 2, lr = lane & 3;
    const size_t bh_base = (size_t)(b * N_HEADS + h) * T_SEQ * 32;
    const size_t vt_base = (size_t)(b * N_HEADS + h) * (T_SEQ / 2) * 64;

    // ---- stage Q tile (128 rows) once
    {
        const unsigned* Qgh = g_qh + bh_base + (size_t)qt * 128 * 32;
        const unsigned* Qgl = g_ql + bh_base + (size_t)qt * 128 * 32;
#pragma unroll
        for (int i = 0; i < 8; i++) {
            int idx = tid + i * 128;
            int row = idx >> 3, c4 = (idx & 7) * 4;
            cp16(&QH[row * AT_SQ + c4], Qgh + row * 32 + c4);
            cp16(&QL[row * AT_SQ + c4], Qgl + row * 32 + c4);
        }
        cp_commit();
        cp_wait<0>();
    }
    __syncthreads();

    auto stage_tile = [&](int kt, int buf) {
        unsigned* KH = Kbuf + buf * KBUF_SZ;
        unsigned* KL = KH + 64 * AT_SK;
        unsigned* VH = Vbuf + buf * VBUF_SZ;
        unsigned* VL = VH + 32 * AT_SV;
        const unsigned* Kgh = g_kh + bh_base + (size_t)kt * 64 * 32;
        const unsigned* Kgl = g_kl + bh_base + (size_t)kt * 64 * 32;
        const unsigned* Vgh = g_vth + vt_base + (size_t)kt * 32 * 64;
        const unsigned* Vgl = g_vtl + vt_base + (size_t)kt * 32 * 64;
#pragma unroll
        for (int i = 0; i < 4; i++) {
            int idx = tid + i * 128;            // 512: 64 rows x 8 chunks
            int row = idx >> 3, c4 = (idx & 7) * 4;
            cp16(&KH[row * AT_SK + c4], Kgh + row * 32 + c4);
            cp16(&KL[row * AT_SK + c4], Kgl + row * 32 + c4);
        }
#pragma unroll
        for (int i = 0; i < 4; i++) {
            int idx = tid + i * 128;            // 512: 32 kp x 16 chunks
            int kp = idx >> 4, c4 = (idx & 15) * 4;
            cp16(&VH[kp * AT_SV + c4], Vgh + kp * 64 + c4);
            cp16(&VL[kp * AT_SV + c4], Vgl + kp * 64 + c4);
        }
        cp_commit();
    };

    float o_acc[2][8][4];
#pragma unroll
    for (int mt = 0; mt < 2; mt++)
#pragma unroll
        for (int n = 0; n < 8; n++)
#pragma unroll
            for (int j = 0; j < 4; j++) o_acc[mt][n][j] = 0.0f;
    float mrow[2][2] = {{-1e30f, -1e30f}, {-1e30f, -1e30f}};
    float lrow[2][2] = {{0.0f, 0.0f}, {0.0f, 0.0f}};

    const int kt_end = 2 * qt + 1;
    stage_tile(0, 0);

    for (int kt = 0; kt <= kt_end; kt++) {
        const int buf = kt & 1;
        if (kt < kt_end) {
            stage_tile(kt + 1, buf ^ 1);
            cp_wait<1>();
        } else {
            cp_wait<0>();
        }
        __syncthreads();

        unsigned* KH = Kbuf + buf * KBUF_SZ;
        unsigned* KL = KH + 64 * AT_SK;
        unsigned* VH = Vbuf + buf * VBUF_SZ;
        unsigned* VL = VH + 32 * AT_SV;

        const bool active = (kt * 64 <= qt * 128 + w * 32 + 31);
        if (active) {
            // ---- S = Q @ K^T
            float s[2][8][4];
#pragma unroll
            for (int mt = 0; mt < 2; mt++)
#pragma unroll
                for (int n = 0; n < 8; n++)
#pragma unroll
                    for (int j = 0; j < 4; j++) s[mt][n][j] = 0.0f;
#pragma unroll
            for (int kk = 0; kk < 4; kk++) {
                const int p = kk * 8 + lr;
                unsigned qhf[2][4], qlf[2][4];
#pragma unroll
                for (int mt = 0; mt < 2; mt++) {
                    int r0 = w * 32 + mt * 16 + lq;
                    qhf[mt][0] = QH[r0 * AT_SQ + p];
                    qhf[mt][1] = QH[(r0 + 8) * AT_SQ + p];
                    qhf[mt][2] = QH[r0 * AT_SQ + p + 4];
                    qhf[mt][3] = QH[(r0 + 8) * AT_SQ + p + 4];
                    qlf[mt][0] = QL[r0 * AT_SQ + p];
                    qlf[mt][1] = QL[(r0 + 8) * AT_SQ + p];
                    qlf[mt][2] = QL[r0 * AT_SQ + p + 4];
                    qlf[mt][3] = QL[(r0 + 8) * AT_SQ + p + 4];
                }
#pragma unroll
                for (int n = 0; n < 8; n++) {
                    int krow = n * 8 + lq;
                    unsigned bh0 = KH[krow * AT_SK + p];
                    unsigned bh1 = KH[krow * AT_SK + p + 4];
                    unsigned bl0 = KL[krow * AT_SK + p];
                    unsigned bl1 = KL[krow * AT_SK + p + 4];
#pragma unroll
                    for (int mt = 0; mt < 2; mt++) {
                        mma_bf16(s[mt][n], qhf[mt], bh0, bh1);
                        mma_bf16(s[mt][n], qhf[mt], bl0, bl1);
                        mma_bf16(s[mt][n], qlf[mt], bh0, bh1);
                    }
                }
            }

            // ---- causal mask (tiles touching the diagonal)
            if ((kt + 1) * 64 > qt * 128 + w * 32) {
#pragma unroll
                for (int mt = 0; mt < 2; mt++) {
                    int qr0 = qt * 128 + w * 32 + mt * 16 + lq;
#pragma unroll
                    for (int n = 0; n < 8; n++) {
                        int kc = kt * 64 + n * 8 + 2 * lr;
                        if (kc     > qr0)     s[mt][n][0] = -1e30f;
                        if (kc + 1 > qr0)     s[mt][n][1] = -1e30f;
                        if (kc     > qr0 + 8) s[mt][n][2] = -1e30f;
                        if (kc + 1 > qr0 + 8) s[mt][n][3] = -1e30f;
                    }
                }
            }

            // ---- online softmax per m16 tile
#pragma unroll
            for (int mt = 0; mt < 2; mt++) {
                float rm0 = -1e30f, rm1 = -1e30f;
#pragma unroll
                for (int n = 0; n < 8; n++) {
                    rm0 = fmaxf(rm0, fmaxf(s[mt][n][0], s[mt][n][1]));
                    rm1 = fmaxf(rm1, fmaxf(s[mt][n][2], s[mt][n][3]));
                }
                rm0 = fmaxf(rm0, __shfl_xor_sync(0xffffffffu, rm0, 1));
                rm0 = fmaxf(rm0, __shfl_xor_sync(0xffffffffu, rm0, 2));
                rm1 = fmaxf(rm1, __shfl_xor_sync(0xffffffffu, rm1, 1));
                rm1 = fmaxf(rm1, __shfl_xor_sync(0xffffffffu, rm1, 2));
                float mn0 = fmaxf(mrow[mt][0], rm0), mn1 = fmaxf(mrow[mt][1], rm1);
                float c0 = __expf(mrow[mt][0] - mn0), c1 = __expf(mrow[mt][1] - mn1);
                mrow[mt][0] = mn0; mrow[mt][1] = mn1;

                int r0 = w * 32 + mt * 16 + lq;
                float ps0 = 0.0f, ps1 = 0.0f;
#pragma unroll
                for (int n = 0; n < 8; n++) {
                    float p00 = __expf(s[mt][n][0] - mn0);
                    float p01 = __expf(s[mt][n][1] - mn0);
                    float p10 = __expf(s[mt][n][2] - mn1);
                    float p11 = __expf(s[mt][n][3] - mn1);
                    ps0 += p00 + p01;
                    ps1 += p10 + p11;
                    unsigned hv, lv;
                    split2(p00, p01, hv, lv);
                    PH[r0 * AT_SQ + n * 4 + lr] = hv;
                    PL[r0 * AT_SQ + n * 4 + lr] = lv;
                    split2(p10, p11, hv, lv);
                    PH[(r0 + 8) * AT_SQ + n * 4 + lr] = hv;
                    PL[(r0 + 8) * AT_SQ + n * 4 + lr] = lv;
                }
                lrow[mt][0] = lrow[mt][0] * c0 + ps0;
                lrow[mt][1] = lrow[mt][1] * c1 + ps1;
#pragma unroll
                for (int n = 0; n < 8; n++) {
                    o_acc[mt][n][0] *= c0; o_acc[mt][n][1] *= c0;
                    o_acc[mt][n][2] *= c1; o_acc[mt][n][3] *= c1;
                }
            }
            __syncwarp();

            // ---- O += P @ V
#pragma unroll
            for (int kk = 0; kk < 4; kk++) {
                const int p = kk * 8 + lr;
                unsigned ahf[2][4], alf[2][4];
#pragma unroll
                for (int mt = 0; mt < 2; mt++) {
                    int r0 = w * 32 + mt * 16 + lq;
                    ahf[mt][0] = PH[r0 * AT_SQ + p];
                    ahf[mt][1] = PH[(r0 + 8) * AT_SQ + p];
                    ahf[mt][2] = PH[r0 * AT_SQ + p + 4];
                    ahf[mt][3] = PH[(r0 + 8) * AT_SQ + p + 4];
                    alf[mt][0] = PL[r0 * AT_SQ + p];
                    alf[mt][1] = PL[(r0 + 8) * AT_SQ + p];
                    alf[mt][2] = PL[r0 * AT_SQ + p + 4];
                    alf[mt][3] = PL[(r0 + 8) * AT_SQ + p + 4];
                }
#pragma unroll
                for (int n = 0; n < 8; n++) {
                    unsigned bh0 = VH[p * AT_SV + n * 8 + lq];
                    unsigned bh1 = VH[(p + 4) * AT_SV + n * 8 + lq];
                    unsigned bl0 = VL[p * AT_SV + n * 8 + lq];
                    unsigned bl1 = VL[(p + 4) * AT_SV + n * 8 + lq];
#pragma unroll
                    for (int mt = 0; mt < 2; mt++) {
                        mma_bf16(o_acc[mt][n], ahf[mt], bh0, bh1);
                        mma_bf16(o_acc[mt][n], ahf[mt], bl0, bl1);
                        mma_bf16(o_acc[mt][n], alf[mt], bh0, bh1);
                    }
                }
            }
            __syncwarp();
        }
        __syncthreads();
    }

    // ---- finalize: normalize and emit out-proj A planes
#pragma unroll
    for (int mt = 0; mt < 2; mt++) {
        float l0 = lrow[mt][0], l1 = lrow[mt][1];
        l0 += __shfl_xor_sync(0xffffffffu, l0, 1);
        l0 += __shfl_xor_sync(0xffffffffu, l0, 2);
        l1 += __shfl_xor_sync(0xffffffffu, l1, 1);
        l1 += __shfl_xor_sync(0xffffffffu, l1, 2);
        float inv0 = 1.0f / l0, inv1 = 1.0f / l1;

        int row0 = b * T_SEQ + qt * 128 + w * 32 + mt * 16 + lq;
#pragma unroll
        for (int n = 0; n < 8; n++) {
            int dp = h * 32 + n * 4 + lr;
            unsigned hv, lv;
            split2(o_acc[mt][n][0] * inv0, o_acc[mt][n][1] * inv0, hv, lv);
            g_ah[(size_t)row0 * KP_MODEL + dp] = hv;
            g_al[(size_t)row0 * KP_MODEL + dp] = lv;
            split2(o_acc[mt][n][2] * inv1, o_acc[mt][n][3] * inv1, hv, lv);
            g_ah[(size_t)(row0 + 8) * KP_MODEL + dp] = hv;
            g_al[(size_t)(row0 + 8) * KP_MODEL + dp] = lv;
        }
    }
}

// ---------------------------------------------------------------------------
extern "C" void kernel_launch(void* const* d_in, const int* in_sizes, int n_in,
                              void* d_out, int out_size)
{
    const float* x    = (const float*)d_in[0];
    const float* Wqkv = (const float*)d_in[1];
    const float* bqkv = (const float*)d_in[2];
    const float* Wo   = (const float*)d_in[3];
    const float* bo   = (const float*)d_in[4];
    float* out = (float*)d_out;

    unsigned *xh, *xl, *wqh, *wql, *woh, *wol, *ah, *al;
    cudaGetSymbolAddress((void**)&xh,  g_xh);
    cudaGetSymbolAddress((void**)&xl,  g_xl);
    cudaGetSymbolAddress((void**)&wqh, g_wqh);
    cudaGetSymbolAddress((void**)&wql, g_wql);
    cudaGetSymbolAddress((void**)&woh, g_woh);
    cudaGetSymbolAddress((void**)&wol, g_wol);
    cudaGetSymbolAddress((void**)&ah,  g_ah);
    cudaGetSymbolAddress((void**)&al,  g_al);

    cudaFuncSetAttribute(gemm_planes<0>, cudaFuncAttributeMaxDynamicSharedMemorySize, GEMM_SMEM);
    cudaFuncSetAttribute(gemm_planes<1>, cudaFuncAttributeMaxDynamicSharedMemorySize, GEMM_SMEM);
    cudaFuncSetAttribute(attn_tc, cudaFuncAttributeMaxDynamicSharedMemorySize, ATTN_SMEM);

    // 0) one-time splits
    {
        int tx = M_TOK * KP_MODEL;
        split_rowpairs<<<(tx + 255) / 256, 256>>>(x, xh, xl, tx);
        int tq = KP_MODEL * N_QKV;
        split_colpairs<<<(tq + 255) / 256, 256>>>(Wqkv, wqh, wql, N_QKV, tq);
        int to = KP_MODEL * D_MODEL;
        split_colpairs<<<(to + 255) / 256, 256>>>(Wo, woh, wol, D_MODEL, to);
    }

    // 1) QKV projection -> head-major split planes
    gemm_planes<1><<<dim3(N_QKV / 128, M_TOK / 256), 256, GEMM_SMEM>>>(
        xh, xl, wqh, wql, bqkv, nullptr, M_TOK, N_QKV, D_MODEL);

    // 1b) transpose V -> key-pair-major planes
    vtrans<<<dim3(T_SEQ / 64, N_HEADS, B_SZ), 256>>>();

    // 2) causal flash attention -> out-proj A planes
    attn_tc<<<dim3(T_SEQ / 128, N_HEADS, B_SZ), 128, ATTN_SMEM>>>();

    // 3) output projection -> fp32 out
    gemm_planes<0><<<dim3(D_MODEL / 128, M_TOK / 256), 256, GEMM_SMEM>>>(
        ah, al, woh, wol, bo, out, M_TOK, D_MODEL, D_MODEL);
}

// round 8
// speedup vs baseline: 1.1499x; 1.1499x over previous
#include <cuda_runtime.h>
#include <cuda_bf16.h>
#include <cstdint>

#define D_MODEL 768
#define KP_MODEL 384            // D/2 (u32 pairs)
#define N_HEADS 12
#define HD      64
#define B_SZ    4
#define T_SEQ   2048
#define M_TOK   (B_SZ * T_SEQ)  // 8192
#define N_QKV   (3 * D_MODEL)   // 2304

// ---------------- static device scratch (hi/lo bf16-pair planes, u32) -------
__device__ unsigned g_xh[(size_t)M_TOK * KP_MODEL],  g_xl[(size_t)M_TOK * KP_MODEL];
__device__ unsigned g_wqh[(size_t)KP_MODEL * N_QKV], g_wql[(size_t)KP_MODEL * N_QKV];
__device__ unsigned g_woh[(size_t)KP_MODEL * D_MODEL], g_wol[(size_t)KP_MODEL * D_MODEL];
// head-major [B][H][T][32] pair planes
#define HM_SZ ((size_t)B_SZ * N_HEADS * T_SEQ * 32)
__device__ unsigned g_qh[HM_SZ], g_ql[HM_SZ];
__device__ unsigned g_kh[HM_SZ], g_kl[HM_SZ];
__device__ unsigned g_vh[HM_SZ], g_vl[HM_SZ];
// V transposed planes: [B][H][T/2 keypairs][64 d] u32
__device__ unsigned g_vth[HM_SZ], g_vtl[HM_SZ];
// attention output planes (A-operand layout for out-proj)
__device__ unsigned g_ah[(size_t)M_TOK * KP_MODEL], g_al[(size_t)M_TOK * KP_MODEL];

// ---------------------------------------------------------------------------
__device__ __forceinline__ void mma_bf16(float c[4], const unsigned a[4],
                                         unsigned b0, unsigned b1)
{
    asm volatile(
        "mma.sync.aligned.m16n8k16.row.col.f32.bf16.bf16.f32 "
        "{%0,%1,%2,%3}, {%4,%5,%6,%7}, {%8,%9}, {%0,%1,%2,%3};\n"
        : "+f"(c[0]), "+f"(c[1]), "+f"(c[2]), "+f"(c[3])
        : "r"(a[0]), "r"(a[1]), "r"(a[2]), "r"(a[3]), "r"(b0), "r"(b1));
}

__device__ __forceinline__ unsigned pack_bf2(float e_lo, float e_hi)
{
    __nv_bfloat162 t = __floats2bfloat162_rn(e_lo, e_hi); // .x -> low half
    return *reinterpret_cast<unsigned*>(&t);
}

__device__ __forceinline__ void split2(float x0, float x1, unsigned& hi, unsigned& lo)
{
    float h0 = __bfloat162float(__float2bfloat16(x0));
    float h1 = __bfloat162float(__float2bfloat16(x1));
    hi = pack_bf2(h0, h1);
    lo = pack_bf2(x0 - h0, x1 - h1);
}

__device__ __forceinline__ float ex2(float x)
{
    float y;
    asm("ex2.approx.f32 %0, %1;" : "=f"(y) : "f"(x));
    return y;
}

__device__ __forceinline__ void cp16(void* dst_smem, const void* src)
{
    unsigned saddr = (unsigned)__cvta_generic_to_shared(dst_smem);
    asm volatile("cp.async.cg.shared.global [%0], [%1], 16;\n" :: "r"(saddr), "l"(src));
}
__device__ __forceinline__ void cp_commit() { asm volatile("cp.async.commit_group;\n"); }
template <int N>
__device__ __forceinline__ void cp_wait() { asm volatile("cp.async.wait_group %0;\n" :: "n"(N)); }

// ---------------------------------------------------------------------------
// Split kernels
// ---------------------------------------------------------------------------
__global__ void split_rowpairs(const float* __restrict__ src,
                               unsigned* __restrict__ H, unsigned* __restrict__ L,
                               int total)
{
    int i = blockIdx.x * blockDim.x + threadIdx.x;
    if (i < total) {
        float2 v = ((const float2*)src)[i];
        unsigned h, l;
        split2(v.x, v.y, h, l);
        H[i] = h; L[i] = l;
    }
}

__global__ void split_colpairs(const float* __restrict__ src,
                               unsigned* __restrict__ H, unsigned* __restrict__ L,
                               int N, int total)
{
    int i = blockIdx.x * blockDim.x + threadIdx.x;
    if (i < total) {
        int kp = i / N, n = i - kp * N;
        float a = src[(size_t)(2 * kp) * N + n];
        float b = src[(size_t)(2 * kp + 1) * N + n];
        unsigned h, l;
        split2(a, b, h, l);
        H[i] = h; L[i] = l;
    }
}

// V transpose: head-major [t][dp] -> key-pair-major [kp][d] planes.
__global__ __launch_bounds__(256) void vtrans()
{
    __shared__ unsigned sH[64 * 33], sL[64 * 33];
    const int ktile = blockIdx.x, h = blockIdx.y, b = blockIdx.z;
    const int tid = threadIdx.x;
    const size_t in_base  = ((size_t)(b * N_HEADS + h) * T_SEQ + ktile * 64) * 32;
    const size_t out_base = ((size_t)(b * N_HEADS + h) * (T_SEQ / 2) + ktile * 32) * 64;

#pragma unroll
    for (int i = 0; i < 8; i++) {
        int idx = tid + i * 256;
        int t = idx >> 5, dp = idx & 31;
        sH[t * 33 + dp] = g_vh[in_base + t * 32 + dp];
        sL[t * 33 + dp] = g_vl[in_base + t * 32 + dp];
    }
    __syncthreads();
#pragma unroll
    for (int i = 0; i < 8; i++) {
        int o = tid + i * 256;
        int kp = o >> 6, d = o & 63;
        unsigned sel = (d & 1) ? 0x7632u : 0x5410u;
        unsigned h0 = sH[(2 * kp) * 33 + (d >> 1)];
        unsigned h1 = sH[(2 * kp + 1) * 33 + (d >> 1)];
        g_vth[out_base + o] = __byte_perm(h0, h1, sel);
        unsigned l0 = sL[(2 * kp) * 33 + (d >> 1)];
        unsigned l1 = sL[(2 * kp + 1) * 33 + (d >> 1)];
        g_vtl[out_base + o] = __byte_perm(l0, l1, sel);
    }
}

// ---------------------------------------------------------------------------
// GEMM (round-5 config: 128 thr = 4 warps, block 128x128, warp 64x64, BK=32)
// ---------------------------------------------------------------------------
#define GA_STR 20
#define GB_STR 136
#define GA_SZ  (128 * GA_STR)
#define GB_SZ  (16 * GB_STR)
#define GBUF   (2 * GA_SZ + 2 * GB_SZ)
#define GEMM_SMEM (2 * GBUF * 4)        // 75776 bytes

template <int EPI>
__global__ __launch_bounds__(128) void gemm_planes(
    const unsigned* __restrict__ Ah, const unsigned* __restrict__ Al,
    const unsigned* __restrict__ Bh, const unsigned* __restrict__ Bl,
    const float* __restrict__ bias, float* __restrict__ Cout,
    int M, int N, int K)
{
    extern __shared__ unsigned sm[];
    const int tid  = threadIdx.x;
    const int lane = tid & 31;
    const int wid  = tid >> 5;
    const int wm   = wid >> 1;
    const int wn   = wid & 1;
    const int lq   = lane >> 2;
    const int lr   = lane & 3;
    const int bm = blockIdx.y, bn = blockIdx.x;
    const int KP = K >> 1;

    float acc[4][8][4];
#pragma unroll
    for (int mt = 0; mt < 4; mt++)
#pragma unroll
        for (int n = 0; n < 8; n++)
#pragma unroll
            for (int j = 0; j < 4; j++) acc[mt][n][j] = 0.0f;

    auto load_tile = [&](int kt, int buf) {
        unsigned* AHs = sm + buf * GBUF;
        unsigned* ALs = AHs + GA_SZ;
        unsigned* BHs = ALs + GA_SZ;
        unsigned* BLs = BHs + GB_SZ;
        const int kp0 = kt * 16;
#pragma unroll
        for (int i = 0; i < 4; i++) {
            int idx = tid + i * 128;
            int row = idx >> 2, c4 = (idx & 3) * 4;
            size_t g = (size_t)(bm * 128 + row) * KP + kp0 + c4;
            cp16(&AHs[row * GA_STR + c4], Ah + g);
            cp16(&ALs[row * GA_STR + c4], Al + g);
        }
#pragma unroll
        for (int i = 0; i < 4; i++) {
            int idx = tid + i * 128;
            int row = idx >> 5, c4 = (idx & 31) * 4;
            size_t g = (size_t)(kp0 + row) * N + bn * 128 + c4;
            cp16(&BHs[row * GB_STR + c4], Bh + g);
            cp16(&BLs[row * GB_STR + c4], Bl + g);
        }
        cp_commit();
    };

    const int KT = K / 32;
    load_tile(0, 0);

    for (int kt = 0; kt < KT; kt++) {
        int buf = kt & 1;
        if (kt + 1 < KT) {
            load_tile(kt + 1, buf ^ 1);
            cp_wait<1>();
        } else {
            cp_wait<0>();
        }
        __syncthreads();

        unsigned* AHs = sm + buf * GBUF;
        unsigned* ALs = AHs + GA_SZ;
        unsigned* BHs = ALs + GA_SZ;
        unsigned* BLs = BHs + GB_SZ;

#pragma unroll
        for (int kk = 0; kk < 2; kk++) {
            unsigned ah[4][4], al[4][4];
            const int p = kk * 8 + lr;
#pragma unroll
            for (int mt = 0; mt < 4; mt++) {
                int r = wm * 64 + mt * 16 + lq;
                ah[mt][0] = AHs[r * GA_STR + p];
                ah[mt][1] = AHs[(r + 8) * GA_STR + p];
                ah[mt][2] = AHs[r * GA_STR + p + 4];
                ah[mt][3] = AHs[(r + 8) * GA_STR + p + 4];
                al[mt][0] = ALs[r * GA_STR + p];
                al[mt][1] = ALs[(r + 8) * GA_STR + p];
                al[mt][2] = ALs[r * GA_STR + p + 4];
                al[mt][3] = ALs[(r + 8) * GA_STR + p + 4];
            }
#pragma unroll
            for (int n = 0; n < 8; n++) {
                int col = wn * 64 + n * 8 + lq;
                unsigned bh0 = BHs[p * GB_STR + col];
                unsigned bh1 = BHs[(p + 4) * GB_STR + col];
                unsigned bl0 = BLs[p * GB_STR + col];
                unsigned bl1 = BLs[(p + 4) * GB_STR + col];
#pragma unroll
                for (int mt = 0; mt < 4; mt++) {
                    mma_bf16(acc[mt][n], ah[mt], bh0, bh1);
                    mma_bf16(acc[mt][n], ah[mt], bl0, bl1);
                    mma_bf16(acc[mt][n], al[mt], bh0, bh1);
                }
            }
        }
        __syncthreads();
    }

    // ---- epilogue
#pragma unroll
    for (int mt = 0; mt < 4; mt++) {
        int row0 = bm * 128 + wm * 64 + mt * 16 + lq;
#pragma unroll
        for (int n = 0; n < 8; n++) {
            int col = bn * 128 + wn * 64 + n * 8 + 2 * lr;
            float b0 = bias[col], b1 = bias[col + 1];
            float x0 = acc[mt][n][0] + b0, x1 = acc[mt][n][1] + b1;
            float y0 = acc[mt][n][2] + b0, y1 = acc[mt][n][3] + b1;
            if (EPI == 0) {
                *(float2*)&Cout[(size_t)row0 * N + col]       = make_float2(x0, x1);
                *(float2*)&Cout[(size_t)(row0 + 8) * N + col] = make_float2(y0, y1);
            } else {
                int seg = col / D_MODEL;
                int nn  = col - seg * D_MODEL;
                int hh2 = nn >> 6;
                int dp  = (nn & 63) >> 1;
                if (seg == 0) {
                    // fold softmax scale AND log2(e) for exp2-domain softmax
                    const float sc = 0.18033688011f;   // 0.125 * log2(e)
                    x0 *= sc; x1 *= sc; y0 *= sc; y1 *= sc;
                }
                unsigned* H = (seg == 0) ? g_qh : (seg == 1) ? g_kh : g_vh;
                unsigned* L = (seg == 0) ? g_ql : (seg == 1) ? g_kl : g_vl;
                int bb = row0 >> 11, t = row0 & 2047;
                size_t o = ((size_t)(bb * N_HEADS + hh2) * T_SEQ + t) * 32 + dp;
                unsigned hv, lv;
                split2(x0, x1, hv, lv);
                H[o] = hv; L[o] = lv;
                split2(y0, y1, hv, lv);
                H[o + 8 * 32] = hv; L[o + 8 * 32] = lv;
            }
        }
    }
}

// ---------------------------------------------------------------------------
// Flash attention (causal), split-bf16 mma, 128-query tiles, P IN REGISTERS.
// 128 thr = 4 warps; warp w owns q rows [w*32, w*32+32).
// Q fragments held in registers for the whole kernel; K + pre-transposed V
// double-buffered via cp.async. No P smem round-trip: S C-frags are re-packed
// directly into PV A-frags.
// Smem (u32): Kbuf 2x{KH/KL[64][36]}, Vbuf 2x{VH/VL[32][72]} = 18432 u32.
// Q staged transiently in the K buffers before the mainloop.
// ---------------------------------------------------------------------------
#define AT_SK 36
#define AT_SV 72
#define KBUF_SZ (2 * 64 * AT_SK)    // 4608 u32
#define VBUF_SZ (2 * 32 * AT_SV)    // 4608 u32
#define ATTN_SMEM ((2 * KBUF_SZ + 2 * VBUF_SZ) * 4)   // 73728 B

__global__ __launch_bounds__(128) void attn_tc()
{
    extern __shared__ unsigned usm[];
    unsigned* Kbuf = usm;                       // 2 x KBUF_SZ
    unsigned* Vbuf = usm + 2 * KBUF_SZ;         // 2 x VBUF_SZ

    const int b = blockIdx.z, h = blockIdx.y;
    const int qt = gridDim.x - 1 - blockIdx.x;  // heavy tiles first
    const int tid = threadIdx.x;
    const int w = tid >> 5, lane = tid & 31;
    const int lq = lane >> 2, lr = lane & 3;
    const size_t bh_base = (size_t)(b * N_HEADS + h) * T_SEQ * 32;
    const size_t vt_base = (size_t)(b * N_HEADS + h) * (T_SEQ / 2) * 64;

    // ---- stage Q tile into K buffers (transient), pull fragments to regs
    unsigned qfh[4][2][4], qfl[4][2][4];
    {
        const unsigned* Qgh = g_qh + bh_base + (size_t)qt * 128 * 32;
        const unsigned* Qgl = g_ql + bh_base + (size_t)qt * 128 * 32;
#pragma unroll
        for (int i = 0; i < 8; i++) {
            int idx = tid + i * 128;            // 1024: 128 rows x 8 chunks
            int row = idx >> 3, c4 = (idx & 7) * 4;
            cp16(&usm[row * AT_SK + c4], Qgh + row * 32 + c4);
            cp16(&usm[128 * AT_SK + row * AT_SK + c4], Qgl + row * 32 + c4);
        }
        cp_commit();
        cp_wait<0>();
        __syncthreads();
#pragma unroll
        for (int kk = 0; kk < 4; kk++) {
            const int p = kk * 8 + lr;
#pragma unroll
            for (int mt = 0; mt < 2; mt++) {
                int r0 = w * 32 + mt * 16 + lq;
                qfh[kk][mt][0] = usm[r0 * AT_SK + p];
                qfh[kk][mt][1] = usm[(r0 + 8) * AT_SK + p];
                qfh[kk][mt][2] = usm[r0 * AT_SK + p + 4];
                qfh[kk][mt][3] = usm[(r0 + 8) * AT_SK + p + 4];
                qfl[kk][mt][0] = usm[128 * AT_SK + r0 * AT_SK + p];
                qfl[kk][mt][1] = usm[128 * AT_SK + (r0 + 8) * AT_SK + p];
                qfl[kk][mt][2] = usm[128 * AT_SK + r0 * AT_SK + p + 4];
                qfl[kk][mt][3] = usm[128 * AT_SK + (r0 + 8) * AT_SK + p + 4];
            }
        }
        __syncthreads();   // Q region will be overwritten by K staging
    }

    auto stage_tile = [&](int kt, int buf) {
        unsigned* KH = Kbuf + buf * KBUF_SZ;
        unsigned* KL = KH + 64 * AT_SK;
        unsigned* VH = Vbuf + buf * VBUF_SZ;
        unsigned* VL = VH + 32 * AT_SV;
        const unsigned* Kgh = g_kh + bh_base + (size_t)kt * 64 * 32;
        const unsigned* Kgl = g_kl + bh_base + (size_t)kt * 64 * 32;
        const unsigned* Vgh = g_vth + vt_base + (size_t)kt * 32 * 64;
        const unsigned* Vgl = g_vtl + vt_base + (size_t)kt * 32 * 64;
#pragma unroll
        for (int i = 0; i < 4; i++) {
            int idx = tid + i * 128;            // 512: 64 rows x 8 chunks
            int row = idx >> 3, c4 = (idx & 7) * 4;
            cp16(&KH[row * AT_SK + c4], Kgh + row * 32 + c4);
            cp16(&KL[row * AT_SK + c4], Kgl + row * 32 + c4);
        }
#pragma unroll
        for (int i = 0; i < 4; i++) {
            int idx = tid + i * 128;            // 512: 32 kp x 16 chunks
            int kp = idx >> 4, c4 = (idx & 15) * 4;
            cp16(&VH[kp * AT_SV + c4], Vgh + kp * 64 + c4);
            cp16(&VL[kp * AT_SV + c4], Vgl + kp * 64 + c4);
        }
        cp_commit();
    };

    float o_acc[2][8][4];
#pragma unroll
    for (int mt = 0; mt < 2; mt++)
#pragma unroll
        for (int n = 0; n < 8; n++)
#pragma unroll
            for (int j = 0; j < 4; j++) o_acc[mt][n][j] = 0.0f;
    float mrow[2][2] = {{-1e30f, -1e30f}, {-1e30f, -1e30f}};
    float lrow[2][2] = {{0.0f, 0.0f}, {0.0f, 0.0f}};

    const int kt_end = 2 * qt + 1;
    stage_tile(0, 0);

    for (int kt = 0; kt <= kt_end; kt++) {
        const int buf = kt & 1;
        if (kt < kt_end) {
            stage_tile(kt + 1, buf ^ 1);
            cp_wait<1>();
        } else {
            cp_wait<0>();
        }
        __syncthreads();

        unsigned* KH = Kbuf + buf * KBUF_SZ;
        unsigned* KL = KH + 64 * AT_SK;
        unsigned* VH = Vbuf + buf * VBUF_SZ;
        unsigned* VL = VH + 32 * AT_SV;

        const bool active = (kt * 64 <= qt * 128 + w * 32 + 31);
        if (active) {
            // ---- S = Q @ K^T  (scores already in log2 domain via Q scale)
            float s[2][8][4];
#pragma unroll
            for (int mt = 0; mt < 2; mt++)
#pragma unroll
                for (int n = 0; n < 8; n++)
#pragma unroll
                    for (int j = 0; j < 4; j++) s[mt][n][j] = 0.0f;
#pragma unroll
            for (int kk = 0; kk < 4; kk++) {
                const int p = kk * 8 + lr;
#pragma unroll
                for (int n = 0; n < 8; n++) {
                    int krow = n * 8 + lq;
                    unsigned bh0 = KH[krow * AT_SK + p];
                    unsigned bh1 = KH[krow * AT_SK + p + 4];
                    unsigned bl0 = KL[krow * AT_SK + p];
                    unsigned bl1 = KL[krow * AT_SK + p + 4];
#pragma unroll
                    for (int mt = 0; mt < 2; mt++) {
                        mma_bf16(s[mt][n], qfh[kk][mt], bh0, bh1);
                        mma_bf16(s[mt][n], qfh[kk][mt], bl0, bl1);
                        mma_bf16(s[mt][n], qfl[kk][mt], bh0, bh1);
                    }
                }
            }

            // ---- causal mask (tiles touching the diagonal)
            if ((kt + 1) * 64 > qt * 128 + w * 32) {
#pragma unroll
                for (int mt = 0; mt < 2; mt++) {
                    int qr0 = qt * 128 + w * 32 + mt * 16 + lq;
#pragma unroll
                    for (int n = 0; n < 8; n++) {
                        int kc = kt * 64 + n * 8 + 2 * lr;
                        if (kc     > qr0)     s[mt][n][0] = -1e30f;
                        if (kc + 1 > qr0)     s[mt][n][1] = -1e30f;
                        if (kc     > qr0 + 8) s[mt][n][2] = -1e30f;
                        if (kc + 1 > qr0 + 8) s[mt][n][3] = -1e30f;
                    }
                }
            }

            // ---- online softmax (exp2 domain); p overwrites s in place
#pragma unroll
            for (int mt = 0; mt < 2; mt++) {
                float rm0 = -1e30f, rm1 = -1e30f;
#pragma unroll
                for (int n = 0; n < 8; n++) {
                    rm0 = fmaxf(rm0, fmaxf(s[mt][n][0], s[mt][n][1]));
                    rm1 = fmaxf(rm1, fmaxf(s[mt][n][2], s[mt][n][3]));
                }
                rm0 = fmaxf(rm0, __shfl_xor_sync(0xffffffffu, rm0, 1));
                rm0 = fmaxf(rm0, __shfl_xor_sync(0xffffffffu, rm0, 2));
                rm1 = fmaxf(rm1, __shfl_xor_sync(0xffffffffu, rm1, 1));
                rm1 = fmaxf(rm1, __shfl_xor_sync(0xffffffffu, rm1, 2));
                float mn0 = fmaxf(mrow[mt][0], rm0), mn1 = fmaxf(mrow[mt][1], rm1);
                float c0 = ex2(mrow[mt][0] - mn0), c1 = ex2(mrow[mt][1] - mn1);
                mrow[mt][0] = mn0; mrow[mt][1] = mn1;

                float ps0 = 0.0f, ps1 = 0.0f;
#pragma unroll
                for (int n = 0; n < 8; n++) {
                    s[mt][n][0] = ex2(s[mt][n][0] - mn0);
                    s[mt][n][1] = ex2(s[mt][n][1] - mn0);
                    s[mt][n][2] = ex2(s[mt][n][2] - mn1);
                    s[mt][n][3] = ex2(s[mt][n][3] - mn1);
                    ps0 += s[mt][n][0] + s[mt][n][1];
                    ps1 += s[mt][n][2] + s[mt][n][3];
                }
                lrow[mt][0] = lrow[mt][0] * c0 + ps0;
                lrow[mt][1] = lrow[mt][1] * c1 + ps1;
#pragma unroll
                for (int n = 0; n < 8; n++) {
                    o_acc[mt][n][0] *= c0; o_acc[mt][n][1] *= c0;
                    o_acc[mt][n][2] *= c1; o_acc[mt][n][3] *= c1;
                }
            }

            // ---- O += P @ V   (P frags built directly from S C-frags)
#pragma unroll
            for (int kk = 0; kk < 4; kk++) {
                const int p = kk * 8 + lr;
                unsigned ahf[2][4], alf[2][4];
#pragma unroll
                for (int mt = 0; mt < 2; mt++) {
                    split2(s[mt][2 * kk][0],     s[mt][2 * kk][1],     ahf[mt][0], alf[mt][0]);
                    split2(s[mt][2 * kk][2],     s[mt][2 * kk][3],     ahf[mt][1], alf[mt][1]);
                    split2(s[mt][2 * kk + 1][0], s[mt][2 * kk + 1][1], ahf[mt][2], alf[mt][2]);
                    split2(s[mt][2 * kk + 1][2], s[mt][2 * kk + 1][3], ahf[mt][3], alf[mt][3]);
                }
#pragma unroll
                for (int n = 0; n < 8; n++) {
                    unsigned bh0 = VH[p * AT_SV + n * 8 + lq];
                    unsigned bh1 = VH[(p + 4) * AT_SV + n * 8 + lq];
                    unsigned bl0 = VL[p * AT_SV + n * 8 + lq];
                    unsigned bl1 = VL[(p + 4) * AT_SV + n * 8 + lq];
#pragma unroll
                    for (int mt = 0; mt < 2; mt++) {
                        mma_bf16(o_acc[mt][n], ahf[mt], bh0, bh1);
                        mma_bf16(o_acc[mt][n], ahf[mt], bl0, bl1);
                        mma_bf16(o_acc[mt][n], alf[mt], bh0, bh1);
                    }
                }
            }
        }
        __syncthreads();   // all warps done with buf before it is restaged
    }

    // ---- finalize: normalize and emit out-proj A planes
#pragma unroll
    for (int mt = 0; mt < 2; mt++) {
        float l0 = lrow[mt][0], l1 = lrow[mt][1];
        l0 += __shfl_xor_sync(0xffffffffu, l0, 1);
        l0 += __shfl_xor_sync(0xffffffffu, l0, 2);
        l1 += __shfl_xor_sync(0xffffffffu, l1, 1);
        l1 += __shfl_xor_sync(0xffffffffu, l1, 2);
        float inv0 = 1.0f / l0, inv1 = 1.0f / l1;

        int row0 = b * T_SEQ + qt * 128 + w * 32 + mt * 16 + lq;
#pragma unroll
        for (int n = 0; n < 8; n++) {
            int dp = h * 32 + n * 4 + lr;
            unsigned hv, lv;
            split2(o_acc[mt][n][0] * inv0, o_acc[mt][n][1] * inv0, hv, lv);
            g_ah[(size_t)row0 * KP_MODEL + dp] = hv;
            g_al[(size_t)row0 * KP_MODEL + dp] = lv;
            split2(o_acc[mt][n][2] * inv1, o_acc[mt][n][3] * inv1, hv, lv);
            g_ah[(size_t)(row0 + 8) * KP_MODEL + dp] = hv;
            g_al[(size_t)(row0 + 8) * KP_MODEL + dp] = lv;
        }
    }
}

// ---------------------------------------------------------------------------
extern "C" void kernel_launch(void* const* d_in, const int* in_sizes, int n_in,
                              void* d_out, int out_size)
{
    const float* x    = (const float*)d_in[0];
    const float* Wqkv = (const float*)d_in[1];
    const float* bqkv = (const float*)d_in[2];
    const float* Wo   = (const float*)d_in[3];
    const float* bo   = (const float*)d_in[4];
    float* out = (float*)d_out;

    unsigned *xh, *xl, *wqh, *wql, *woh, *wol, *ah, *al;
    cudaGetSymbolAddress((void**)&xh,  g_xh);
    cudaGetSymbolAddress((void**)&xl,  g_xl);
    cudaGetSymbolAddress((void**)&wqh, g_wqh);
    cudaGetSymbolAddress((void**)&wql, g_wql);
    cudaGetSymbolAddress((void**)&woh, g_woh);
    cudaGetSymbolAddress((void**)&wol, g_wol);
    cudaGetSymbolAddress((void**)&ah,  g_ah);
    cudaGetSymbolAddress((void**)&al,  g_al);

    cudaFuncSetAttribute(gemm_planes<0>, cudaFuncAttributeMaxDynamicSharedMemorySize, GEMM_SMEM);
    cudaFuncSetAttribute(gemm_planes<1>, cudaFuncAttributeMaxDynamicSharedMemorySize, GEMM_SMEM);
    cudaFuncSetAttribute(attn_tc, cudaFuncAttributeMaxDynamicSharedMemorySize, ATTN_SMEM);

    // 0) one-time splits
    {
        int tx = M_TOK * KP_MODEL;
        split_rowpairs<<<(tx + 255) / 256, 256>>>(x, xh, xl, tx);
        int tq = KP_MODEL * N_QKV;
        split_colpairs<<<(tq + 255) / 256, 256>>>(Wqkv, wqh, wql, N_QKV, tq);
        int to = KP_MODEL * D_MODEL;
        split_colpairs<<<(to + 255) / 256, 256>>>(Wo, woh, wol, D_MODEL, to);
    }

    // 1) QKV projection -> head-major split planes
    gemm_planes<1><<<dim3(N_QKV / 128, M_TOK / 128), 128, GEMM_SMEM>>>(
        xh, xl, wqh, wql, bqkv, nullptr, M_TOK, N_QKV, D_MODEL);

    // 1b) transpose V -> key-pair-major planes
    vtrans<<<dim3(T_SEQ / 64, N_HEADS, B_SZ), 256>>>();

    // 2) causal flash attention -> out-proj A planes
    attn_tc<<<dim3(T_SEQ / 128, N_HEADS, B_SZ), 128, ATTN_SMEM>>>();

    // 3) output projection -> fp32 out
    gemm_planes<0><<<dim3(D_MODEL / 128, M_TOK / 128), 128, GEMM_SMEM>>>(
        ah, al, woh, wol, bo, out, M_TOK, D_MODEL, D_MODEL);
}